// round 16
// baseline (speedup 1.0000x reference)
#include <cuda_runtime.h>
#include <cstdint>

#define N_NODES 4096
#define D_FEAT  256
#define N_EDGES 65536

// ------------------------- static device scratch -------------------------
static __device__ float g_sraw[N_EDGES];
static __device__ unsigned g_minb, g_maxb;
static __device__ int   g_deg[N_NODES];
static __device__ int   g_rowptr[N_NODES + 1];
static __device__ int   g_fill[N_NODES];
static __device__ unsigned long long g_csr_key[N_EDGES];   // (score_bits<<32)|eid
static __device__ int   g_csr_dst[N_EDGES];
static __device__ float g_tot[N_NODES];
static __device__ int   g_cntN[N_NODES];
static __device__ float g_avg[N_NODES];
static __device__ __align__(16) unsigned short g_mem[N_NODES][8];
static __device__ int   g_msz[N_NODES];
static __device__ unsigned long long g_khi[N_NODES], g_klo[N_NODES];
static __device__ __align__(16) unsigned short g_uniq[N_NODES][8];
static __device__ int   g_usz[N_NODES];
static __device__ int   g_U;
static __device__ int   g_n2uptr[N_NODES + 1];
static __device__ int   g_n2ulist[N_NODES * 8];
static __device__ int   g_sel[N_NODES];
static __device__ int   g_K;
static __device__ int   g_c2ptr[N_NODES + 1];
static __device__ int   g_c2list[N_NODES * 8];
static __device__ unsigned char g_B[(size_t)N_NODES * N_NODES];   // cluster adj bitmap
static __device__ int   g_rn[N_NODES], g_roff[N_NODES + 1];

// ------------------------- kernels -------------------------

__global__ void k_init() {
    int i = blockIdx.x * blockDim.x + threadIdx.x;
    if (i < N_NODES) {
        g_deg[i] = 0; g_fill[i] = 0;
        g_tot[i] = 0.f; g_cntN[i] = 0;
    }
    if (i == 0) { g_minb = 0x7f800000u; g_maxb = 0u; }
}

// one warp per edge: fp32 distance (float4 loads), degree count, global min/max
__global__ void k_dist(const float* __restrict__ x, const int* __restrict__ ei) {
    int warp = threadIdx.x >> 5, lane = threadIdx.x & 31;
    int e = blockIdx.x * 8 + warp;
    __shared__ float smin[8], smax[8];
    float sval = __int_as_float(0x7f800000);
    {
        int u = ei[e], v = ei[N_EDGES + e];
        const float4* xu = (const float4*)(x + (size_t)u * D_FEAT);
        const float4* xv = (const float4*)(x + (size_t)v * D_FEAT);
        float acc = 0.f;
        #pragma unroll
        for (int i = 0; i < 2; i++) {
            float4 a = xu[lane + 32 * i], b = xv[lane + 32 * i];
            float d0 = a.x - b.x, d1 = a.y - b.y, d2 = a.z - b.z, d3 = a.w - b.w;
            acc = fmaf(d0, d0, acc);
            acc = fmaf(d1, d1, acc);
            acc = fmaf(d2, d2, acc);
            acc = fmaf(d3, d3, acc);
        }
        #pragma unroll
        for (int o = 16; o; o >>= 1) acc += __shfl_down_sync(0xffffffffu, acc, o);
        if (lane == 0) {
            float s = sqrtf(acc + 1e-12f);
            g_sraw[e] = s;
            atomicAdd(&g_deg[u], 1);
            sval = s;
        }
    }
    if (lane == 0) { smin[warp] = sval; smax[warp] = sval; }
    __syncthreads();
    if (threadIdx.x == 0) {
        float mn = smin[0], mx = smax[0];
        #pragma unroll
        for (int i = 1; i < 8; i++) { mn = fminf(mn, smin[i]); mx = fmaxf(mx, smax[i]); }
        atomicMin(&g_minb, __float_as_uint(mn));
        atomicMax(&g_maxb, __float_as_uint(mx));
    }
}

// exclusive scan of a fixed 4096-int array selected by `which`
__global__ void k_scan4096(int which) {
    const int* in; int* out;
    if (which == 0) { in = g_deg; out = g_rowptr; }
    else            { in = g_rn;  out = g_roff;   }
    __shared__ int sh[1024];
    int t = threadIdx.x;
    int v0 = in[t * 4 + 0], v1 = in[t * 4 + 1], v2 = in[t * 4 + 2], v3 = in[t * 4 + 3];
    int s = v0 + v1 + v2 + v3;
    sh[t] = s; __syncthreads();
    for (int off = 1; off < 1024; off <<= 1) {
        int a = (t >= off) ? sh[t - off] : 0;
        __syncthreads();
        sh[t] += a;
        __syncthreads();
    }
    int pre = t ? sh[t - 1] : 0;
    out[t * 4 + 0] = pre;
    out[t * 4 + 1] = pre + v0;
    out[t * 4 + 2] = pre + v0 + v1;
    out[t * 4 + 3] = pre + v0 + v1 + v2;
    if (t == 1023) out[4096] = sh[1023];
}

__global__ void k_norm_fill(const int* __restrict__ ei) {
    int e = blockIdx.x * 256 + threadIdx.x;
    float mn = __uint_as_float(g_minb), mx = __uint_as_float(g_maxb);
    float s = (g_sraw[e] - mn) / (mx - mn) + 0.5f;
    int u = ei[e], v = ei[N_EDGES + e];
    atomicAdd(&g_tot[u], s); atomicAdd(&g_tot[v], s);
    atomicAdd(&g_cntN[u], 1); atomicAdd(&g_cntN[v], 1);
    int slot = g_rowptr[u] + atomicAdd(&g_fill[u], 1);
    g_csr_key[slot] = ((unsigned long long)__float_as_uint(s) << 32) | (unsigned)e;
    g_csr_dst[slot] = v;
}

// warp-per-seed Prim-style growth with per-row cached best candidates.
// Prologue: first 4096 threads compute g_avg (consumed only by k_outputs).
__global__ void __launch_bounds__(256) k_grow() {   // <<<512,256>>>
    int gid = blockIdx.x * 256 + threadIdx.x;
    if (gid < N_NODES) g_avg[gid] = g_tot[gid] / (float)g_cntN[gid];

    int wid = threadIdx.x >> 5, lane = threadIdx.x & 31;
    int seed = blockIdx.x * 8 + wid;
    unsigned short joined[8];
    unsigned long long ck[8];
    int cd[8];
    #pragma unroll
    for (int j = 0; j < 8; j++) { joined[j] = 0xFFFF; ck[j] = ~0ull; cd[j] = -1; }
    joined[0] = (unsigned short)seed;
    int nj = 1; float tot = 0.f;

    // initial scan of seed row
    {
        unsigned long long bk = ~0ull; int bd = -1;
        int p0 = g_rowptr[seed], p1 = g_rowptr[seed + 1];
        for (int p = p0 + lane; p < p1; p += 32) {
            int d = g_csr_dst[p];
            bool in = false;
            #pragma unroll
            for (int j = 0; j < 8; j++) in |= (j < nj) && (joined[j] == (unsigned short)d);
            if (!in) {
                unsigned long long key = g_csr_key[p];
                if (key < bk) { bk = key; bd = d; }
            }
        }
        #pragma unroll
        for (int o = 16; o; o >>= 1) {
            unsigned long long ok = __shfl_down_sync(0xffffffffu, bk, o);
            int od = __shfl_down_sync(0xffffffffu, bd, o);
            if (ok < bk) { bk = ok; bd = od; }
        }
        bk = __shfl_sync(0xffffffffu, bk, 0);
        bd = __shfl_sync(0xffffffffu, bd, 0);
        ck[0] = bk; cd[0] = bd;
    }

    while (tot < 3.0f && nj < 8) {
        unsigned long long bk = ~0ull; int bd = -1;
        #pragma unroll
        for (int r = 0; r < 8; r++) if (r < nj && ck[r] < bk) { bk = ck[r]; bd = cd[r]; }
        if (bd < 0) break;
        tot += __uint_as_float((unsigned)(bk >> 32));
        joined[nj] = (unsigned short)bd;
        nj++;
        // rescan rows whose cached best just joined, and scan the new row
        #pragma unroll
        for (int r = 0; r < 8; r++) {
            if (r < nj && (cd[r] == bd || r == nj - 1)) {
                int u = joined[r];
                unsigned long long nk = ~0ull; int nd = -1;
                int p0 = g_rowptr[u], p1 = g_rowptr[u + 1];
                for (int p = p0 + lane; p < p1; p += 32) {
                    int d = g_csr_dst[p];
                    bool in = false;
                    #pragma unroll
                    for (int j = 0; j < 8; j++) in |= (j < nj) && (joined[j] == (unsigned short)d);
                    if (!in) {
                        unsigned long long key = g_csr_key[p];
                        if (key < nk) { nk = key; nd = d; }
                    }
                }
                #pragma unroll
                for (int o = 16; o; o >>= 1) {
                    unsigned long long ok = __shfl_down_sync(0xffffffffu, nk, o);
                    int od = __shfl_down_sync(0xffffffffu, nd, o);
                    if (ok < nk) { nk = ok; nd = od; }
                }
                nk = __shfl_sync(0xffffffffu, nk, 0);
                nd = __shfl_sync(0xffffffffu, nd, 0);
                ck[r] = nk; cd[r] = nd;
            }
        }
    }

    if (lane == 0) {
        // sort members ascending (0xFFFF sentinels to the end)
        unsigned short memb[8];
        #pragma unroll
        for (int j = 0; j < 8; j++) memb[j] = joined[j];
        #pragma unroll
        for (int a = 0; a < 7; a++)
            #pragma unroll
            for (int b = 0; b < 7 - a; b++) {
                unsigned short x0 = memb[b], x1 = memb[b + 1];
                memb[b] = (x0 < x1) ? x0 : x1;
                memb[b + 1] = (x0 < x1) ? x1 : x0;
            }
        #pragma unroll
        for (int j = 0; j < 8; j++) g_mem[seed][j] = memb[j];
        g_msz[seed] = nj;
        unsigned long long hi = 0, lo = 0;
        #pragma unroll
        for (int j = 0; j < 7; j++) {
            unsigned long long k = (j < nj) ? (unsigned long long)(8191u - memb[j]) : 0ull;
            if (j < 4) hi |= k << (48 - 16 * j);
            else       lo |= k << (48 - 16 * (j - 4));
        }
        g_khi[seed] = hi; g_klo[seed] = lo;   // lo bits [0:16) free
    }
}

// compare-exchange for the register-resident bitonic passes
#define CMPX(a, b, up) do { \
    bool _g = (H[a] > H[b]) || (H[a] == H[b] && L[a] > L[b]); \
    if (_g == (up)) { \
        unsigned long long _th = H[a]; H[a] = H[b]; H[b] = _th; \
        unsigned long long _tl = L[a]; L[a] = L[b]; L[b] = _tl; \
    } \
} while (0)

// single-block bitonic sort of 4096 128-bit keys (idx packed in lo[0:16)).
// Final j=2,1 passes of each stage run in registers. Fused with
// adjacent-dedup + compaction + node->cluster CSR build.
__global__ void k_sort_dedup() {   // <<<1,1024, 65536>>>
    extern __shared__ unsigned long long sk[];   // [2*4096]
    __shared__ int sh[1024];
    int t = threadIdx.x;
    for (int r = t; r < N_NODES; r += 1024) {
        sk[2 * r] = g_khi[r];
        sk[2 * r + 1] = g_klo[r] | (unsigned long long)r;
    }
    __syncthreads();
    for (int k = 2; k <= N_NODES; k <<= 1) {
        for (int j = k >> 1; j >= 4; j >>= 1) {
            for (int r = t; r < N_NODES; r += 1024) {
                int x = r ^ j;
                if (x > r) {
                    unsigned long long ah = sk[2 * r], al = sk[2 * r + 1];
                    unsigned long long bh = sk[2 * x], bl = sk[2 * x + 1];
                    bool agtb = (ah > bh) || (ah == bh && al > bl);
                    bool up = ((r & k) == 0);
                    if (agtb == up) {
                        sk[2 * r] = bh; sk[2 * r + 1] = bl;
                        sk[2 * x] = ah; sk[2 * x + 1] = al;
                    }
                }
            }
            __syncthreads();
        }
        // register-resident j=2 (k>=4) and j=1 passes within the quad
        {
            int r0 = t * 4;
            unsigned long long H[4], L[4];
            #pragma unroll
            for (int q = 0; q < 4; q++) { H[q] = sk[2 * (r0 + q)]; L[q] = sk[2 * (r0 + q) + 1]; }
            if (k >= 4) {
                bool up = ((r0 & k) == 0);
                CMPX(0, 2, up); CMPX(1, 3, up);   // j = 2
                CMPX(0, 1, up); CMPX(2, 3, up);   // j = 1
            } else {
                CMPX(0, 1, true);
                CMPX(2, 3, false);
            }
            #pragma unroll
            for (int q = 0; q < 4; q++) { sk[2 * (r0 + q)] = H[q]; sk[2 * (r0 + q) + 1] = L[q]; }
        }
        __syncthreads();
    }
    // dedup on (hi, lo & ~0xFFFF)
    int fl[4], loc[4];
    int s = 0;
    #pragma unroll
    for (int q = 0; q < 4; q++) {
        int r = t * 4 + q;
        int f;
        if (r == 0) f = 1;
        else {
            unsigned long long ph = sk[2 * (r - 1)], pl = sk[2 * (r - 1) + 1] & ~0xFFFFull;
            unsigned long long ch = sk[2 * r],       cl = sk[2 * r + 1] & ~0xFFFFull;
            f = (ph != ch) || (pl != cl);
        }
        fl[q] = f; loc[q] = s; s += f;
    }
    sh[t] = s; __syncthreads();
    for (int off = 1; off < 1024; off <<= 1) {
        int a = (t >= off) ? sh[t - off] : 0;
        __syncthreads();
        sh[t] += a;
        __syncthreads();
    }
    int pre = t ? sh[t - 1] : 0;
    #pragma unroll
    for (int q = 0; q < 4; q++) {
        int r = t * 4 + q;
        if (fl[q]) {
            int pos = pre + loc[q];
            int src = (int)(sk[2 * r + 1] & 0xFFFFull);
            #pragma unroll
            for (int j = 0; j < 8; j++) g_uniq[pos][j] = g_mem[src][j];
            g_usz[pos] = g_msz[src];
        }
    }
    if (t == 1023) g_U = sh[1023];
    __syncthreads();
    int U = g_U;
    // ---- fused node->cluster CSR build (reuse sk as int scratch) ----
    int* cnt = (int*)sk;               // [0..4096)
    int* ptr = ((int*)sk) + 4096;      // [4096..8193)
    int* fil = ((int*)sk) + 8200;      // [8200..12296)
    for (int i = t; i < N_NODES; i += 1024) cnt[i] = 0;
    __syncthreads();
    for (int u = t; u < U; u += 1024) {
        int sz = g_usz[u];
        for (int mi = 0; mi < sz; mi++) atomicAdd(&cnt[g_uniq[u][mi]], 1);
    }
    __syncthreads();
    {
        int v0 = cnt[t * 4 + 0], v1 = cnt[t * 4 + 1], v2 = cnt[t * 4 + 2], v3 = cnt[t * 4 + 3];
        int ss = v0 + v1 + v2 + v3;
        sh[t] = ss; __syncthreads();
        for (int off = 1; off < 1024; off <<= 1) {
            int a = (t >= off) ? sh[t - off] : 0;
            __syncthreads();
            sh[t] += a;
            __syncthreads();
        }
        int pr = t ? sh[t - 1] : 0;
        ptr[t * 4 + 0] = pr;
        ptr[t * 4 + 1] = pr + v0;
        ptr[t * 4 + 2] = pr + v0 + v1;
        ptr[t * 4 + 3] = pr + v0 + v1 + v2;
        if (t == 1023) ptr[4096] = sh[1023];
    }
    __syncthreads();
    for (int i = t; i <= N_NODES; i += 1024) g_n2uptr[i] = ptr[i];
    for (int i = t; i < N_NODES; i += 1024) fil[i] = 0;
    __syncthreads();
    for (int u = t; u < U; u += 1024) {
        int sz = g_usz[u];
        for (int mi = 0; mi < sz; mi++) {
            int m = g_uniq[u][mi];
            int slot = ptr[m] + atomicAdd(&fil[m], 1);
            g_n2ulist[slot] = u;
        }
    }
}

// ---------------- single-warp greedy max-cover: phase-descending exact sweep ----
// Register-resident candidate mask + u8 per-window upper bounds (stale bounds
// remain valid upper bounds since counts only decrease).
#define G_OFF_CNT   0         // u32[4096]
#define G_OFF_PTR   16384     // int[4097] (pad to 16400)
#define G_OFF_UQ    32784     // u16[4096*8]
#define G_OFF_SZ    98320     // u8[4096]
#define G_OFF_LS    102416    // u16[32768]
#define G_OFF_COV   167952    // u32[128]
#define G_OFF_WMX   168464    // u8[128]
#define G_SMEM_TOT  168592

__global__ void k_greedy() {   // <<<1,256, G_SMEM_TOT>>>
    extern __shared__ unsigned char sg[];
    unsigned* s_cnt      = (unsigned*)(sg + G_OFF_CNT);
    int* s_ptr           = (int*)(sg + G_OFF_PTR);
    unsigned short* s_uq = (unsigned short*)(sg + G_OFF_UQ);
    unsigned char* s_sz  = (unsigned char*)(sg + G_OFF_SZ);
    unsigned short* s_ls = (unsigned short*)(sg + G_OFF_LS);
    unsigned* s_cov      = (unsigned*)(sg + G_OFF_COV);
    unsigned char* s_wmx = (unsigned char*)(sg + G_OFF_WMX);

    int t = threadIdx.x;
    int U = g_U;
    int T = g_n2uptr[N_NODES];

    for (int i = t; i < 128; i += 256) s_cov[i] = 0;
    for (int c = t; c < N_NODES; c += 256) {
        int cc = (c < U) ? g_usz[c] : 0;
        s_cnt[c] = (unsigned)cc;
        s_sz[c] = (unsigned char)cc;
        ((uint4*)s_uq)[c] = ((const uint4*)g_uniq)[c];
    }
    for (int i = t; i <= N_NODES; i += 256) s_ptr[i] = g_n2uptr[i];
    for (int i = t; i < T; i += 256) s_ls[i] = (unsigned short)g_n2ulist[i];
    __syncthreads();
    if (t < 128) {
        unsigned mx = 0;
        #pragma unroll 8
        for (int q = 0; q < 32; q++) mx = max(mx, s_cnt[t * 32 + q]);
        s_wmx[t] = (unsigned char)mx;
    }
    __syncthreads();
    if (t >= 32) return;

    int lane = t;
    int covered = 0, K = 0;
    for (int phase = 7; phase >= 1 && covered < N_NODES; phase--) {
        for (int w = 0; w < 128 && covered < N_NODES; w++) {
            if ((int)s_wmx[w] < phase) continue;
            int base = w << 5;
            unsigned cc = s_cnt[base + lane];
            unsigned mask = __ballot_sync(0xffffffffu, (int)cc == phase);
            while (mask && covered < N_NODES) {
                int i = __ffs(mask) - 1;
                int c = base + i;
                if (lane == 0) g_sel[K & (N_NODES - 1)] = c;
                K++;
                // ---- mark newly covered members (sz <= 7, lane-parallel) ----
                int sz = s_sz[c];
                int m = (lane < sz) ? (int)s_uq[c * 8 + lane] : -1;
                bool isnew = false;
                if (m >= 0) {
                    unsigned wv = s_cov[m >> 5];
                    isnew = !((wv >> (m & 31)) & 1u);
                }
                if (isnew) atomicOr(&s_cov[m >> 5], 1u << (m & 31));
                unsigned nb = __ballot_sync(0xffffffffu, isnew);
                covered += __popc(nb);
                // ---- per-lane serial decrements; record in-window victims ----
                unsigned rem = 0;
                if (isnew) {
                    int p0 = s_ptr[m], p1 = s_ptr[m + 1];
                    for (int p = p0; p < p1; p++) {
                        int c2 = (int)s_ls[p];
                        atomicSub(&s_cnt[c2], 1u);
                        unsigned d = (unsigned)(c2 - base);
                        if (d < 32u) rem |= 1u << d;
                    }
                }
                rem = __reduce_or_sync(0xffffffffu, rem);
                __syncwarp();
                mask &= ~rem;
                mask &= (i == 31) ? 0u : ~((2u << i) - 1u);   // clear bits <= i
            }
            // refresh the window bound from settled counts (valid for later phases)
            unsigned ccnow = s_cnt[base + lane];
            unsigned mx = __reduce_max_sync(0xffffffffu, ccnow);
            if (lane == 0) s_wmx[w] = (unsigned char)mx;
        }
    }
    if (lane == 0) g_K = K;
}

// fused c2 count + scan + fill (single block, 1024 threads)
__global__ void k_c2() {   // <<<1,1024, 49184>>>
    extern __shared__ int sc[];
    int* cnt = sc;            // [0..4096)
    int* ptr = sc + 4096;     // [4096..8193)
    int* fil = sc + 8200;     // [8200..12296)
    __shared__ int sh[1024];
    int t = threadIdx.x;
    int K = g_K;
    for (int i = t; i < N_NODES; i += 1024) cnt[i] = 0;
    __syncthreads();
    for (int k = t; k < K; k += 1024) {
        int c = g_sel[k];
        int sz = g_usz[c];
        for (int mi = 0; mi < sz; mi++) atomicAdd(&cnt[g_uniq[c][mi]], 1);
    }
    __syncthreads();
    {
        int v0 = cnt[t * 4 + 0], v1 = cnt[t * 4 + 1], v2 = cnt[t * 4 + 2], v3 = cnt[t * 4 + 3];
        int ss = v0 + v1 + v2 + v3;
        sh[t] = ss; __syncthreads();
        for (int off = 1; off < 1024; off <<= 1) {
            int a = (t >= off) ? sh[t - off] : 0;
            __syncthreads();
            sh[t] += a;
            __syncthreads();
        }
        int pr = t ? sh[t - 1] : 0;
        ptr[t * 4 + 0] = pr;
        ptr[t * 4 + 1] = pr + v0;
        ptr[t * 4 + 2] = pr + v0 + v1;
        ptr[t * 4 + 3] = pr + v0 + v1 + v2;
        if (t == 1023) ptr[4096] = sh[1023];
    }
    __syncthreads();
    for (int i = t; i <= N_NODES; i += 1024) g_c2ptr[i] = ptr[i];
    for (int i = t; i < N_NODES; i += 1024) fil[i] = 0;
    __syncthreads();
    for (int k = t; k < K; k += 1024) {
        int c = g_sel[k];
        int sz = g_usz[c];
        for (int mi = 0; mi < sz; mi++) {
            int m = g_uniq[c][mi];
            int slot = ptr[m] + atomicAdd(&fil[m], 1);
            g_c2list[slot] = k;
        }
    }
}

__global__ void k_clearB() {
    int tot16 = (g_K * N_NODES) >> 4;
    int stride = gridDim.x * blockDim.x;
    uint4 z = make_uint4(0, 0, 0, 0);
    uint4* B4 = (uint4*)g_B;
    for (int i = blockIdx.x * blockDim.x + threadIdx.x; i < tot16; i += stride)
        B4[i] = z;
}

__global__ void k_markB(const int* __restrict__ ei) {
    int e = blockIdx.x * 256 + threadIdx.x;
    int u = ei[e], v = ei[N_EDGES + e];
    int a0 = g_c2ptr[u], a1 = g_c2ptr[u + 1];
    int b0 = g_c2ptr[v], b1 = g_c2ptr[v + 1];
    for (int p = a0; p < a1; p++) {
        size_t base = (size_t)g_c2list[p] * N_NODES;
        for (int q = b0; q < b1; q++) g_B[base + g_c2list[q]] = 1;
    }
}

// warp-per-row popcount of adjacency rows (limited to K cols)
__global__ void k_rowcnt() {   // <<<512,256>>>
    int gw = (blockIdx.x * blockDim.x + threadIdx.x) >> 5;
    int lane = threadIdx.x & 31;
    if (gw >= N_NODES) return;
    int K = g_K;
    if (gw >= K) { if (lane == 0) g_rn[gw] = 0; return; }
    const unsigned* row = (const unsigned*)(g_B + (size_t)gw * N_NODES);
    int words = (K + 3) >> 2;
    int c = 0;
    for (int j = lane; j < words; j += 32) c += __popc(row[j]);
    #pragma unroll
    for (int o = 16; o; o >>= 1) c += __shfl_down_sync(0xffffffffu, c, o);
    if (lane == 0) g_rn[gw] = c - (int)g_B[(size_t)gw * N_NODES + gw];
}

// warp-per-row ballot compaction into the edge list
__global__ void k_write_edges(float* __restrict__ out) {   // <<<512,256>>>
    int gw = (blockIdx.x * blockDim.x + threadIdx.x) >> 5;
    int lane = threadIdx.x & 31;
    if (gw >= N_NODES) return;
    int K = g_K;
    if (gw >= K) return;
    int nnz = g_roff[K];
    const unsigned char* row = g_B + (size_t)gw * N_NODES;
    int p = g_roff[gw];
    for (int base = 0; base < K; base += 32) {
        int j = base + lane;
        bool v = (j < K) && (j != gw) && (row[j] != 0);
        unsigned m = __ballot_sync(0xffffffffu, v);
        if (v) {
            int off = __popc(m & ((1u << lane) - 1));
            out[p + off] = (float)gw;
            out[nnz + p + off] = (float)j;
        }
        p += __popc(m);
    }
}

// fused outputs: S rows, Ms rows, x_new, edge_index copy
__global__ void k_outputs(const float* __restrict__ x, const int* __restrict__ ei,
                          float* __restrict__ out) {   // <<<8704,256>>>
    int b = blockIdx.x, t = threadIdx.x;
    int K = g_K;
    int nnz = g_roff[K];
    size_t offX = 2 * (size_t)nnz;
    size_t offS = offX + (size_t)K * D_FEAT;
    size_t offM = offS + (size_t)K * N_NODES;
    size_t offE = offM + (size_t)K * N_NODES;
    if (b < 4096) {
        if (b >= K) return;
        int c = g_sel[b];
        int sz = g_usz[c];
        unsigned short mb[8];
        #pragma unroll
        for (int j = 0; j < 8; j++) mb[j] = (j < sz) ? g_uniq[c][j] : 0xFFFF;
        size_t baseS = offS + (size_t)b * N_NODES;
        size_t baseM = offM + (size_t)b * N_NODES;
        for (int j = t; j < N_NODES; j += 256) {
            bool in = false;
            #pragma unroll
            for (int q = 0; q < 8; q++) in |= (mb[q] == (unsigned short)j);
            float mv = in ? g_avg[j] : 0.f;
            out[baseS + j] = in ? 1.f : 0.f;
            out[baseM + j] = mv;
        }
    } else if (b < 8192) {
        int k = b - 4096;
        if (k >= K) return;
        int c = g_sel[k];
        int sz = g_usz[c];
        float acc = 0.f;
        for (int mi = 0; mi < sz; mi++) {
            int m = g_uniq[c][mi];
            acc += g_avg[m] * x[(size_t)m * D_FEAT + t];
        }
        out[offX + (size_t)k * D_FEAT + t] = acc;
    } else {
        int i = (b - 8192) * 256 + t;
        out[offE + i] = (float)ei[i];
    }
}

// ------------------------- launch -------------------------
extern "C" void kernel_launch(void* const* d_in, const int* in_sizes, int n_in,
                              void* d_out, int out_size) {
    const float* x  = (const float*)d_in[0];
    const int*   ei = (const int*)d_in[1];
    float*       out = (float*)d_out;
    cudaStream_t st = cudaStreamPerThread;

    cudaFuncSetAttribute(k_sort_dedup, cudaFuncAttributeMaxDynamicSharedMemorySize, 65536);
    cudaFuncSetAttribute(k_greedy, cudaFuncAttributeMaxDynamicSharedMemorySize, G_SMEM_TOT);
    cudaFuncSetAttribute(k_c2, cudaFuncAttributeMaxDynamicSharedMemorySize, 49184);

    k_init       <<<16, 256, 0, st>>>();
    k_dist       <<<N_EDGES / 8, 256, 0, st>>>(x, ei);
    k_scan4096   <<<1, 1024, 0, st>>>(0);            // deg -> rowptr
    k_norm_fill  <<<N_EDGES / 256, 256, 0, st>>>(ei);
    k_grow       <<<512, 256, 0, st>>>();
    k_sort_dedup <<<1, 1024, 65536, st>>>();
    k_greedy     <<<1, 256, G_SMEM_TOT, st>>>();
    k_c2         <<<1, 1024, 49184, st>>>();
    k_clearB     <<<512, 256, 0, st>>>();
    k_markB      <<<N_EDGES / 256, 256, 0, st>>>(ei);
    k_rowcnt     <<<512, 256, 0, st>>>();
    k_scan4096   <<<1, 1024, 0, st>>>(1);            // rn -> roff
    k_write_edges<<<512, 256, 0, st>>>(out);
    k_outputs    <<<8704, 256, 0, st>>>(x, ei, out);
}

// round 17
// speedup vs baseline: 1.0198x; 1.0198x over previous
#include <cuda_runtime.h>
#include <cstdint>

#define N_NODES 4096
#define D_FEAT  256
#define N_EDGES 65536

// ------------------------- static device scratch -------------------------
static __device__ float g_sraw[N_EDGES];
static __device__ unsigned g_minb, g_maxb;
static __device__ int   g_deg[N_NODES];
static __device__ int   g_rowptr[N_NODES + 1];
static __device__ int   g_fill[N_NODES];
static __device__ unsigned long long g_csr_key[N_EDGES];   // (score_bits<<32)|eid
static __device__ int   g_csr_dst[N_EDGES];
static __device__ float g_tot[N_NODES];
static __device__ int   g_cntN[N_NODES];
static __device__ float g_avg[N_NODES];
static __device__ __align__(16) unsigned short g_mem[N_NODES][8];
static __device__ int   g_msz[N_NODES];
static __device__ unsigned long long g_khi[N_NODES], g_klo[N_NODES];
static __device__ __align__(16) unsigned short g_uniq[N_NODES][8];
static __device__ int   g_usz[N_NODES];
static __device__ int   g_U;
static __device__ int   g_n2uptr[N_NODES + 1];
static __device__ int   g_n2ulist[N_NODES * 8];
static __device__ int   g_sel[N_NODES];
static __device__ int   g_K;
static __device__ int   g_c2ptr[N_NODES + 1];
static __device__ int   g_c2list[N_NODES * 8];
static __device__ unsigned char g_B[(size_t)N_NODES * N_NODES];   // cluster adj bitmap
static __device__ int   g_rn[N_NODES], g_roff[N_NODES + 1];

// ------------------------- kernels -------------------------

__global__ void k_init() {
    int i = blockIdx.x * blockDim.x + threadIdx.x;
    if (i < N_NODES) {
        g_deg[i] = 0; g_fill[i] = 0;
        g_tot[i] = 0.f; g_cntN[i] = 0;
    }
    if (i == 0) { g_minb = 0x7f800000u; g_maxb = 0u; }
}

// one warp per edge: fp32 distance (float4 loads), degree count, global min/max
__global__ void k_dist(const float* __restrict__ x, const int* __restrict__ ei) {
    int warp = threadIdx.x >> 5, lane = threadIdx.x & 31;
    int e = blockIdx.x * 8 + warp;
    __shared__ float smin[8], smax[8];
    float sval = __int_as_float(0x7f800000);
    {
        int u = ei[e], v = ei[N_EDGES + e];
        const float4* xu = (const float4*)(x + (size_t)u * D_FEAT);
        const float4* xv = (const float4*)(x + (size_t)v * D_FEAT);
        float acc = 0.f;
        #pragma unroll
        for (int i = 0; i < 2; i++) {
            float4 a = xu[lane + 32 * i], b = xv[lane + 32 * i];
            float d0 = a.x - b.x, d1 = a.y - b.y, d2 = a.z - b.z, d3 = a.w - b.w;
            acc = fmaf(d0, d0, acc);
            acc = fmaf(d1, d1, acc);
            acc = fmaf(d2, d2, acc);
            acc = fmaf(d3, d3, acc);
        }
        #pragma unroll
        for (int o = 16; o; o >>= 1) acc += __shfl_down_sync(0xffffffffu, acc, o);
        if (lane == 0) {
            float s = sqrtf(acc + 1e-12f);
            g_sraw[e] = s;
            atomicAdd(&g_deg[u], 1);
            sval = s;
        }
    }
    if (lane == 0) { smin[warp] = sval; smax[warp] = sval; }
    __syncthreads();
    if (threadIdx.x == 0) {
        float mn = smin[0], mx = smax[0];
        #pragma unroll
        for (int i = 1; i < 8; i++) { mn = fminf(mn, smin[i]); mx = fmaxf(mx, smax[i]); }
        atomicMin(&g_minb, __float_as_uint(mn));
        atomicMax(&g_maxb, __float_as_uint(mx));
    }
}

// exclusive scan of a fixed 4096-int array selected by `which`
__global__ void k_scan4096(int which) {
    const int* in; int* out;
    if (which == 0) { in = g_deg; out = g_rowptr; }
    else            { in = g_rn;  out = g_roff;   }
    __shared__ int sh[1024];
    int t = threadIdx.x;
    int v0 = in[t * 4 + 0], v1 = in[t * 4 + 1], v2 = in[t * 4 + 2], v3 = in[t * 4 + 3];
    int s = v0 + v1 + v2 + v3;
    sh[t] = s; __syncthreads();
    for (int off = 1; off < 1024; off <<= 1) {
        int a = (t >= off) ? sh[t - off] : 0;
        __syncthreads();
        sh[t] += a;
        __syncthreads();
    }
    int pre = t ? sh[t - 1] : 0;
    out[t * 4 + 0] = pre;
    out[t * 4 + 1] = pre + v0;
    out[t * 4 + 2] = pre + v0 + v1;
    out[t * 4 + 3] = pre + v0 + v1 + v2;
    if (t == 1023) out[4096] = sh[1023];
}

__global__ void k_norm_fill(const int* __restrict__ ei) {
    int e = blockIdx.x * 256 + threadIdx.x;
    float mn = __uint_as_float(g_minb), mx = __uint_as_float(g_maxb);
    float s = (g_sraw[e] - mn) / (mx - mn) + 0.5f;
    int u = ei[e], v = ei[N_EDGES + e];
    atomicAdd(&g_tot[u], s); atomicAdd(&g_tot[v], s);
    atomicAdd(&g_cntN[u], 1); atomicAdd(&g_cntN[v], 1);
    int slot = g_rowptr[u] + atomicAdd(&g_fill[u], 1);
    g_csr_key[slot] = ((unsigned long long)__float_as_uint(s) << 32) | (unsigned)e;
    g_csr_dst[slot] = v;
}

__global__ void k_avg() {
    int i = blockIdx.x * blockDim.x + threadIdx.x;
    if (i < N_NODES) g_avg[i] = g_tot[i] / (float)g_cntN[i];
}

// warp-per-seed Prim-style growth with per-row cached best candidates.
// A cached row-min only invalidates when its dst joins the cluster.
__global__ void __launch_bounds__(256) k_grow() {   // <<<512,256>>>
    int wid = threadIdx.x >> 5, lane = threadIdx.x & 31;
    int seed = blockIdx.x * 8 + wid;
    unsigned short joined[8];
    unsigned long long ck[8];
    int cd[8];
    #pragma unroll
    for (int j = 0; j < 8; j++) { joined[j] = 0xFFFF; ck[j] = ~0ull; cd[j] = -1; }
    joined[0] = (unsigned short)seed;
    int nj = 1; float tot = 0.f;

    // initial scan of seed row
    {
        unsigned long long bk = ~0ull; int bd = -1;
        int p0 = g_rowptr[seed], p1 = g_rowptr[seed + 1];
        for (int p = p0 + lane; p < p1; p += 32) {
            int d = g_csr_dst[p];
            bool in = false;
            #pragma unroll
            for (int j = 0; j < 8; j++) in |= (j < nj) && (joined[j] == (unsigned short)d);
            if (!in) {
                unsigned long long key = g_csr_key[p];
                if (key < bk) { bk = key; bd = d; }
            }
        }
        #pragma unroll
        for (int o = 16; o; o >>= 1) {
            unsigned long long ok = __shfl_down_sync(0xffffffffu, bk, o);
            int od = __shfl_down_sync(0xffffffffu, bd, o);
            if (ok < bk) { bk = ok; bd = od; }
        }
        bk = __shfl_sync(0xffffffffu, bk, 0);
        bd = __shfl_sync(0xffffffffu, bd, 0);
        ck[0] = bk; cd[0] = bd;
    }

    while (tot < 3.0f && nj < 8) {
        unsigned long long bk = ~0ull; int bd = -1;
        #pragma unroll
        for (int r = 0; r < 8; r++) if (r < nj && ck[r] < bk) { bk = ck[r]; bd = cd[r]; }
        if (bd < 0) break;
        tot += __uint_as_float((unsigned)(bk >> 32));
        joined[nj] = (unsigned short)bd;
        nj++;
        // rescan rows whose cached best just joined, and scan the new row
        #pragma unroll
        for (int r = 0; r < 8; r++) {
            if (r < nj && (cd[r] == bd || r == nj - 1)) {
                int u = joined[r];
                unsigned long long nk = ~0ull; int nd = -1;
                int p0 = g_rowptr[u], p1 = g_rowptr[u + 1];
                for (int p = p0 + lane; p < p1; p += 32) {
                    int d = g_csr_dst[p];
                    bool in = false;
                    #pragma unroll
                    for (int j = 0; j < 8; j++) in |= (j < nj) && (joined[j] == (unsigned short)d);
                    if (!in) {
                        unsigned long long key = g_csr_key[p];
                        if (key < nk) { nk = key; nd = d; }
                    }
                }
                #pragma unroll
                for (int o = 16; o; o >>= 1) {
                    unsigned long long ok = __shfl_down_sync(0xffffffffu, nk, o);
                    int od = __shfl_down_sync(0xffffffffu, nd, o);
                    if (ok < nk) { nk = ok; nd = od; }
                }
                nk = __shfl_sync(0xffffffffu, nk, 0);
                nd = __shfl_sync(0xffffffffu, nd, 0);
                ck[r] = nk; cd[r] = nd;
            }
        }
    }

    if (lane == 0) {
        // sort members ascending (0xFFFF sentinels to the end)
        unsigned short memb[8];
        #pragma unroll
        for (int j = 0; j < 8; j++) memb[j] = joined[j];
        #pragma unroll
        for (int a = 0; a < 7; a++)
            #pragma unroll
            for (int b = 0; b < 7 - a; b++) {
                unsigned short x0 = memb[b], x1 = memb[b + 1];
                memb[b] = (x0 < x1) ? x0 : x1;
                memb[b + 1] = (x0 < x1) ? x1 : x0;
            }
        #pragma unroll
        for (int j = 0; j < 8; j++) g_mem[seed][j] = memb[j];
        g_msz[seed] = nj;
        unsigned long long hi = 0, lo = 0;
        #pragma unroll
        for (int j = 0; j < 7; j++) {
            unsigned long long k = (j < nj) ? (unsigned long long)(8191u - memb[j]) : 0ull;
            if (j < 4) hi |= k << (48 - 16 * j);
            else       lo |= k << (48 - 16 * (j - 4));
        }
        g_khi[seed] = hi; g_klo[seed] = lo;   // lo bits [0:16) free
    }
}

// compare-exchange for the register-resident bitonic passes
#define CMPX(a, b, up) do { \
    bool _g = (H[a] > H[b]) || (H[a] == H[b] && L[a] > L[b]); \
    if (_g == (up)) { \
        unsigned long long _th = H[a]; H[a] = H[b]; H[b] = _th; \
        unsigned long long _tl = L[a]; L[a] = L[b]; L[b] = _tl; \
    } \
} while (0)

// single-block bitonic sort of 4096 128-bit keys (idx packed in lo[0:16)).
// Final j=2,1 passes of each stage run in registers. Fused with
// adjacent-dedup + compaction + node->cluster CSR build.
__global__ void k_sort_dedup() {   // <<<1,1024, 65536>>>
    extern __shared__ unsigned long long sk[];   // [2*4096]
    __shared__ int sh[1024];
    int t = threadIdx.x;
    for (int r = t; r < N_NODES; r += 1024) {
        sk[2 * r] = g_khi[r];
        sk[2 * r + 1] = g_klo[r] | (unsigned long long)r;
    }
    __syncthreads();
    for (int k = 2; k <= N_NODES; k <<= 1) {
        for (int j = k >> 1; j >= 4; j >>= 1) {
            for (int r = t; r < N_NODES; r += 1024) {
                int x = r ^ j;
                if (x > r) {
                    unsigned long long ah = sk[2 * r], al = sk[2 * r + 1];
                    unsigned long long bh = sk[2 * x], bl = sk[2 * x + 1];
                    bool agtb = (ah > bh) || (ah == bh && al > bl);
                    bool up = ((r & k) == 0);
                    if (agtb == up) {
                        sk[2 * r] = bh; sk[2 * r + 1] = bl;
                        sk[2 * x] = ah; sk[2 * x + 1] = al;
                    }
                }
            }
            __syncthreads();
        }
        // register-resident j=2 (k>=4) and j=1 passes within the quad
        {
            int r0 = t * 4;
            unsigned long long H[4], L[4];
            #pragma unroll
            for (int q = 0; q < 4; q++) { H[q] = sk[2 * (r0 + q)]; L[q] = sk[2 * (r0 + q) + 1]; }
            if (k >= 4) {
                bool up = ((r0 & k) == 0);
                CMPX(0, 2, up); CMPX(1, 3, up);   // j = 2
                CMPX(0, 1, up); CMPX(2, 3, up);   // j = 1
            } else {
                CMPX(0, 1, true);
                CMPX(2, 3, false);
            }
            #pragma unroll
            for (int q = 0; q < 4; q++) { sk[2 * (r0 + q)] = H[q]; sk[2 * (r0 + q) + 1] = L[q]; }
        }
        __syncthreads();
    }
    // dedup on (hi, lo & ~0xFFFF)
    int fl[4], loc[4];
    int s = 0;
    #pragma unroll
    for (int q = 0; q < 4; q++) {
        int r = t * 4 + q;
        int f;
        if (r == 0) f = 1;
        else {
            unsigned long long ph = sk[2 * (r - 1)], pl = sk[2 * (r - 1) + 1] & ~0xFFFFull;
            unsigned long long ch = sk[2 * r],       cl = sk[2 * r + 1] & ~0xFFFFull;
            f = (ph != ch) || (pl != cl);
        }
        fl[q] = f; loc[q] = s; s += f;
    }
    sh[t] = s; __syncthreads();
    for (int off = 1; off < 1024; off <<= 1) {
        int a = (t >= off) ? sh[t - off] : 0;
        __syncthreads();
        sh[t] += a;
        __syncthreads();
    }
    int pre = t ? sh[t - 1] : 0;
    #pragma unroll
    for (int q = 0; q < 4; q++) {
        int r = t * 4 + q;
        if (fl[q]) {
            int pos = pre + loc[q];
            int src = (int)(sk[2 * r + 1] & 0xFFFFull);
            #pragma unroll
            for (int j = 0; j < 8; j++) g_uniq[pos][j] = g_mem[src][j];
            g_usz[pos] = g_msz[src];
        }
    }
    if (t == 1023) g_U = sh[1023];
    __syncthreads();
    int U = g_U;
    // ---- fused node->cluster CSR build (reuse sk as int scratch) ----
    int* cnt = (int*)sk;               // [0..4096)
    int* ptr = ((int*)sk) + 4096;      // [4096..8193)
    int* fil = ((int*)sk) + 8200;      // [8200..12296)
    for (int i = t; i < N_NODES; i += 1024) cnt[i] = 0;
    __syncthreads();
    for (int u = t; u < U; u += 1024) {
        int sz = g_usz[u];
        for (int mi = 0; mi < sz; mi++) atomicAdd(&cnt[g_uniq[u][mi]], 1);
    }
    __syncthreads();
    {
        int v0 = cnt[t * 4 + 0], v1 = cnt[t * 4 + 1], v2 = cnt[t * 4 + 2], v3 = cnt[t * 4 + 3];
        int ss = v0 + v1 + v2 + v3;
        sh[t] = ss; __syncthreads();
        for (int off = 1; off < 1024; off <<= 1) {
            int a = (t >= off) ? sh[t - off] : 0;
            __syncthreads();
            sh[t] += a;
            __syncthreads();
        }
        int pr = t ? sh[t - 1] : 0;
        ptr[t * 4 + 0] = pr;
        ptr[t * 4 + 1] = pr + v0;
        ptr[t * 4 + 2] = pr + v0 + v1;
        ptr[t * 4 + 3] = pr + v0 + v1 + v2;
        if (t == 1023) ptr[4096] = sh[1023];
    }
    __syncthreads();
    for (int i = t; i <= N_NODES; i += 1024) g_n2uptr[i] = ptr[i];
    for (int i = t; i < N_NODES; i += 1024) fil[i] = 0;
    __syncthreads();
    for (int u = t; u < U; u += 1024) {
        int sz = g_usz[u];
        for (int mi = 0; mi < sz; mi++) {
            int m = g_uniq[u][mi];
            int slot = ptr[m] + atomicAdd(&fil[m], 1);
            g_n2ulist[slot] = u;
        }
    }
}

// ---------------- single-warp greedy max-cover: phase-descending exact sweep ----
// Register-resident candidate mask (counts only decrease => clusters can leave
// candidacy but never enter mid-window). 1024-thread load phase; warp 0 runs
// the loop. __reduce_or_sync provides the warp sync — no extra __syncwarp.
#define G_OFF_CNT   0         // u32[4096]
#define G_OFF_PTR   16384     // int[4097] (pad to 16400)
#define G_OFF_UQ    32784     // u16[4096*8]
#define G_OFF_SZ    98320     // u8[4096]
#define G_OFF_LS    102416    // u16[32768]
#define G_OFF_COV   167952    // u32[128]
#define G_SMEM_TOT  168464

__global__ void k_greedy() {   // <<<1,1024, G_SMEM_TOT>>>
    extern __shared__ unsigned char sg[];
    unsigned* s_cnt      = (unsigned*)(sg + G_OFF_CNT);
    int* s_ptr           = (int*)(sg + G_OFF_PTR);
    unsigned short* s_uq = (unsigned short*)(sg + G_OFF_UQ);
    unsigned char* s_sz  = (unsigned char*)(sg + G_OFF_SZ);
    unsigned short* s_ls = (unsigned short*)(sg + G_OFF_LS);
    unsigned* s_cov      = (unsigned*)(sg + G_OFF_COV);

    int t = threadIdx.x;
    int U = g_U;
    int T = g_n2uptr[N_NODES];

    for (int i = t; i < 128; i += 1024) s_cov[i] = 0;
    for (int c = t; c < N_NODES; c += 1024) {
        int cc = (c < U) ? g_usz[c] : 0;
        s_cnt[c] = (unsigned)cc;
        s_sz[c] = (unsigned char)cc;
        ((uint4*)s_uq)[c] = ((const uint4*)g_uniq)[c];
    }
    for (int i = t; i <= N_NODES; i += 1024) s_ptr[i] = g_n2uptr[i];
    for (int i = t; i < T; i += 1024) s_ls[i] = (unsigned short)g_n2ulist[i];
    __syncthreads();
    if (t >= 32) return;

    int lane = t;
    int covered = 0, K = 0;
    for (int phase = 7; phase >= 1 && covered < N_NODES; phase--) {
        for (int base = 0; base < N_NODES && covered < N_NODES; base += 32) {
            unsigned cc = s_cnt[base + lane];
            unsigned mask = __ballot_sync(0xffffffffu, (int)cc == phase);
            while (mask && covered < N_NODES) {
                int i = __ffs(mask) - 1;
                int c = base + i;
                if (lane == 0) g_sel[K & (N_NODES - 1)] = c;
                K++;
                // ---- mark newly covered members (sz <= 7, lane-parallel) ----
                int sz = s_sz[c];
                int m = (lane < sz) ? (int)s_uq[c * 8 + lane] : -1;
                bool isnew = false;
                if (m >= 0) {
                    unsigned w = s_cov[m >> 5];
                    isnew = !((w >> (m & 31)) & 1u);
                }
                if (isnew) atomicOr(&s_cov[m >> 5], 1u << (m & 31));
                unsigned nb = __ballot_sync(0xffffffffu, isnew);
                covered += __popc(nb);
                // ---- per-lane serial decrements; record in-window victims ----
                unsigned rem = 0;
                if (isnew) {
                    int p0 = s_ptr[m], p1 = s_ptr[m + 1];
                    for (int p = p0; p < p1; p++) {
                        int c2 = (int)s_ls[p];
                        atomicSub(&s_cnt[c2], 1u);
                        unsigned d = (unsigned)(c2 - base);
                        if (d < 32u) rem |= 1u << d;
                    }
                }
                rem = __reduce_or_sync(0xffffffffu, rem);   // full warp sync
                mask &= ~rem;
                mask &= (i == 31) ? 0u : ~((2u << i) - 1u);   // clear bits <= i
            }
        }
    }
    if (lane == 0) g_K = K;
}

// fused c2 count + scan + fill (single block, 1024 threads)
__global__ void k_c2() {   // <<<1,1024, 49184>>>
    extern __shared__ int sc[];
    int* cnt = sc;            // [0..4096)
    int* ptr = sc + 4096;     // [4096..8193)
    int* fil = sc + 8200;     // [8200..12296)
    __shared__ int sh[1024];
    int t = threadIdx.x;
    int K = g_K;
    for (int i = t; i < N_NODES; i += 1024) cnt[i] = 0;
    __syncthreads();
    for (int k = t; k < K; k += 1024) {
        int c = g_sel[k];
        int sz = g_usz[c];
        for (int mi = 0; mi < sz; mi++) atomicAdd(&cnt[g_uniq[c][mi]], 1);
    }
    __syncthreads();
    {
        int v0 = cnt[t * 4 + 0], v1 = cnt[t * 4 + 1], v2 = cnt[t * 4 + 2], v3 = cnt[t * 4 + 3];
        int ss = v0 + v1 + v2 + v3;
        sh[t] = ss; __syncthreads();
        for (int off = 1; off < 1024; off <<= 1) {
            int a = (t >= off) ? sh[t - off] : 0;
            __syncthreads();
            sh[t] += a;
            __syncthreads();
        }
        int pr = t ? sh[t - 1] : 0;
        ptr[t * 4 + 0] = pr;
        ptr[t * 4 + 1] = pr + v0;
        ptr[t * 4 + 2] = pr + v0 + v1;
        ptr[t * 4 + 3] = pr + v0 + v1 + v2;
        if (t == 1023) ptr[4096] = sh[1023];
    }
    __syncthreads();
    for (int i = t; i <= N_NODES; i += 1024) g_c2ptr[i] = ptr[i];
    for (int i = t; i < N_NODES; i += 1024) fil[i] = 0;
    __syncthreads();
    for (int k = t; k < K; k += 1024) {
        int c = g_sel[k];
        int sz = g_usz[c];
        for (int mi = 0; mi < sz; mi++) {
            int m = g_uniq[c][mi];
            int slot = ptr[m] + atomicAdd(&fil[m], 1);
            g_c2list[slot] = k;
        }
    }
}

__global__ void k_clearB() {
    int tot16 = (g_K * N_NODES) >> 4;
    int stride = gridDim.x * blockDim.x;
    uint4 z = make_uint4(0, 0, 0, 0);
    uint4* B4 = (uint4*)g_B;
    for (int i = blockIdx.x * blockDim.x + threadIdx.x; i < tot16; i += stride)
        B4[i] = z;
}

__global__ void k_markB(const int* __restrict__ ei) {
    int e = blockIdx.x * 256 + threadIdx.x;
    int u = ei[e], v = ei[N_EDGES + e];
    int a0 = g_c2ptr[u], a1 = g_c2ptr[u + 1];
    int b0 = g_c2ptr[v], b1 = g_c2ptr[v + 1];
    for (int p = a0; p < a1; p++) {
        size_t base = (size_t)g_c2list[p] * N_NODES;
        for (int q = b0; q < b1; q++) g_B[base + g_c2list[q]] = 1;
    }
}

// warp-per-row popcount of adjacency rows (limited to K cols)
__global__ void k_rowcnt() {   // <<<512,256>>>
    int gw = (blockIdx.x * blockDim.x + threadIdx.x) >> 5;
    int lane = threadIdx.x & 31;
    if (gw >= N_NODES) return;
    int K = g_K;
    if (gw >= K) { if (lane == 0) g_rn[gw] = 0; return; }
    const unsigned* row = (const unsigned*)(g_B + (size_t)gw * N_NODES);
    int words = (K + 3) >> 2;
    int c = 0;
    for (int j = lane; j < words; j += 32) c += __popc(row[j]);
    #pragma unroll
    for (int o = 16; o; o >>= 1) c += __shfl_down_sync(0xffffffffu, c, o);
    if (lane == 0) g_rn[gw] = c - (int)g_B[(size_t)gw * N_NODES + gw];
}

// warp-per-row ballot compaction into the edge list
__global__ void k_write_edges(float* __restrict__ out) {   // <<<512,256>>>
    int gw = (blockIdx.x * blockDim.x + threadIdx.x) >> 5;
    int lane = threadIdx.x & 31;
    if (gw >= N_NODES) return;
    int K = g_K;
    if (gw >= K) return;
    int nnz = g_roff[K];
    const unsigned char* row = g_B + (size_t)gw * N_NODES;
    int p = g_roff[gw];
    for (int base = 0; base < K; base += 32) {
        int j = base + lane;
        bool v = (j < K) && (j != gw) && (row[j] != 0);
        unsigned m = __ballot_sync(0xffffffffu, v);
        if (v) {
            int off = __popc(m & ((1u << lane) - 1));
            out[p + off] = (float)gw;
            out[nnz + p + off] = (float)j;
        }
        p += __popc(m);
    }
}

// fused outputs: S rows, Ms rows, x_new, edge_index copy
__global__ void k_outputs(const float* __restrict__ x, const int* __restrict__ ei,
                          float* __restrict__ out) {   // <<<8704,256>>>
    int b = blockIdx.x, t = threadIdx.x;
    int K = g_K;
    int nnz = g_roff[K];
    size_t offX = 2 * (size_t)nnz;
    size_t offS = offX + (size_t)K * D_FEAT;
    size_t offM = offS + (size_t)K * N_NODES;
    size_t offE = offM + (size_t)K * N_NODES;
    if (b < 4096) {
        if (b >= K) return;
        int c = g_sel[b];
        int sz = g_usz[c];
        unsigned short mb[8];
        #pragma unroll
        for (int j = 0; j < 8; j++) mb[j] = (j < sz) ? g_uniq[c][j] : 0xFFFF;
        size_t baseS = offS + (size_t)b * N_NODES;
        size_t baseM = offM + (size_t)b * N_NODES;
        for (int j = t; j < N_NODES; j += 256) {
            bool in = false;
            #pragma unroll
            for (int q = 0; q < 8; q++) in |= (mb[q] == (unsigned short)j);
            float mv = in ? g_avg[j] : 0.f;
            out[baseS + j] = in ? 1.f : 0.f;
            out[baseM + j] = mv;
        }
    } else if (b < 8192) {
        int k = b - 4096;
        if (k >= K) return;
        int c = g_sel[k];
        int sz = g_usz[c];
        float acc = 0.f;
        for (int mi = 0; mi < sz; mi++) {
            int m = g_uniq[c][mi];
            acc += g_avg[m] * x[(size_t)m * D_FEAT + t];
        }
        out[offX + (size_t)k * D_FEAT + t] = acc;
    } else {
        int i = (b - 8192) * 256 + t;
        out[offE + i] = (float)ei[i];
    }
}

// ------------------------- launch -------------------------
extern "C" void kernel_launch(void* const* d_in, const int* in_sizes, int n_in,
                              void* d_out, int out_size) {
    const float* x  = (const float*)d_in[0];
    const int*   ei = (const int*)d_in[1];
    float*       out = (float*)d_out;
    cudaStream_t st = cudaStreamPerThread;

    cudaFuncSetAttribute(k_sort_dedup, cudaFuncAttributeMaxDynamicSharedMemorySize, 65536);
    cudaFuncSetAttribute(k_greedy, cudaFuncAttributeMaxDynamicSharedMemorySize, G_SMEM_TOT);
    cudaFuncSetAttribute(k_c2, cudaFuncAttributeMaxDynamicSharedMemorySize, 49184);

    k_init       <<<16, 256, 0, st>>>();
    k_dist       <<<N_EDGES / 8, 256, 0, st>>>(x, ei);
    k_scan4096   <<<1, 1024, 0, st>>>(0);            // deg -> rowptr
    k_norm_fill  <<<N_EDGES / 256, 256, 0, st>>>(ei);
    k_avg        <<<16, 256, 0, st>>>();
    k_grow       <<<512, 256, 0, st>>>();
    k_sort_dedup <<<1, 1024, 65536, st>>>();
    k_greedy     <<<1, 1024, G_SMEM_TOT, st>>>();
    k_c2         <<<1, 1024, 49184, st>>>();
    k_clearB     <<<512, 256, 0, st>>>();
    k_markB      <<<N_EDGES / 256, 256, 0, st>>>(ei);
    k_rowcnt     <<<512, 256, 0, st>>>();
    k_scan4096   <<<1, 1024, 0, st>>>(1);            // rn -> roff
    k_write_edges<<<512, 256, 0, st>>>(out);
    k_outputs    <<<8704, 256, 0, st>>>(x, ei, out);
}